// round 2
// baseline (speedup 1.0000x reference)
#include <cuda_runtime.h>

#define TPB 256

typedef unsigned long long u64;

// ---------------- packed f32x2 helpers (Blackwell FFMA2 path) --------------
__device__ __forceinline__ u64 pack2(float lo, float hi) {
    u64 r;
    asm("mov.b64 %0, {%1, %2};" : "=l"(r) : "r"(__float_as_uint(lo)), "r"(__float_as_uint(hi)));
    return r;
}
__device__ __forceinline__ u64 dup2(float x) {
    u64 r;
    unsigned u = __float_as_uint(x);
    asm("mov.b64 %0, {%1, %1};" : "=l"(r) : "r"(u));
    return r;
}
__device__ __forceinline__ float2 unpack2(u64 v) {
    unsigned lo, hi;
    asm("mov.b64 {%0, %1}, %2;" : "=r"(lo), "=r"(hi) : "l"(v));
    return make_float2(__uint_as_float(lo), __uint_as_float(hi));
}
__device__ __forceinline__ u64 fma2(u64 a, u64 b, u64 c) {
    u64 d;
    asm("fma.rn.f32x2 %0, %1, %2, %3;" : "=l"(d) : "l"(a), "l"(b), "l"(c));
    return d;
}

__device__ __forceinline__ float fast_tanh(float x) {
    // tanh(x) = 1 - 2/(e^{2x}+1); saturates correctly to +/-1 at large |x|
    float e = __expf(2.0f * x);
    return 1.0f - __fdividef(2.0f, e + 1.0f);
}

// ---------------- 4-qubit real statevector (wire 0 = MSB) ------------------
template <int W>
__device__ __forceinline__ void ry_gate(float* psi, float c, float s) {
    const int bit = 8 >> W;
#pragma unroll
    for (int i = 0; i < 16; i++) {
        if ((i & bit) == 0) {
            const int j = i | bit;
            float a = psi[i], b = psi[j];
            psi[i] = fmaf(c, a, -s * b);
            psi[j] = fmaf(s, a, c * b);
        }
    }
}

template <int CTRL, int TGT>
__device__ __forceinline__ void cnot_gate(float* psi) {
    const int cb = 8 >> CTRL, tb = 8 >> TGT;
#pragma unroll
    for (int i = 0; i < 16; i++) {
        if ((i & cb) && !(i & tb)) {
            const int j = i | tb;
            float t = psi[i];
            psi[i] = psi[j];
            psi[j] = t;
        }
    }
}

__global__ __launch_bounds__(TPB, 2) void qnet_kernel(
    const float* __restrict__ state,  // (B,64)
    const float* __restrict__ W1,     // (32,64)
    const float* __restrict__ b1,     // (32)
    const float* __restrict__ W2,     // (4,32)
    const float* __restrict__ b2,     // (4)
    const float* __restrict__ qp,     // (8)
    const float* __restrict__ H1,     // (32,4)
    const float* __restrict__ c1,     // (32)
    const float* __restrict__ H2,     // (16,32)
    const float* __restrict__ c2,     // (16)
    float* __restrict__ out,          // (B,16)
    int half)                         // B/2
{
    // ---- shared weights (transposed/interleaved so output pairs are contiguous)
    __shared__ __align__(16) float sW1t[64 * 32];  // [k][j]
    __shared__ __align__(16) float sW2t[32 * 4];   // [k][i]
    __shared__ __align__(16) float sH1p[4 * 32];   // [k][o]
    __shared__ __align__(16) float sH2p[32 * 16];  // [k][o]
    __shared__ __align__(16) float sb1[32];
    __shared__ __align__(16) float sc1[32];
    __shared__ __align__(16) float sc2[16];
    __shared__ __align__(16) float sb2[4];
    __shared__ float sqc[8], sqs[8];

    const int tid = threadIdx.x;

#pragma unroll
    for (int i = tid; i < 2048; i += TPB) {           // W1 transpose
        int j = i >> 6, k = i & 63;
        sW1t[k * 32 + j] = W1[i];
    }
    if (tid < 128) {                                  // W2 transpose
        int i = tid >> 5, k = tid & 31;
        sW2t[k * 4 + i] = W2[tid];
    }
    if (tid < 128) {                                  // H1 transpose
        int o = tid >> 2, k = tid & 3;
        sH1p[k * 32 + o] = H1[tid];
    }
#pragma unroll
    for (int i = tid; i < 512; i += TPB) {            // H2 transpose
        int o = i >> 5, k = i & 31;
        sH2p[k * 16 + o] = H2[i];
    }
    if (tid < 32) sb1[tid] = b1[tid];
    if (tid < 32) sc1[tid] = c1[tid];
    if (tid < 16) sc2[tid] = c2[tid];
    if (tid < 4)  sb2[tid] = b2[tid];
    if (tid < 8) {
        float cc, ss;
        sincosf(0.5f * qp[tid], &ss, &cc);
        sqc[tid] = cc;
        sqs[tid] = ss;
    }
    __syncthreads();

    const int g = blockIdx.x * TPB + tid;
    if (g >= half) return;

    // =================== layer 1: h = relu(x @ W1^T + b1), packed over j ===
    u64 a0[16], a1[16];
    {
        const u64* bp = reinterpret_cast<const u64*>(sb1);
#pragma unroll
        for (int p = 0; p < 16; p++) { a0[p] = bp[p]; a1[p] = bp[p]; }
    }
    const float4* x0 = reinterpret_cast<const float4*>(state) + (size_t)g * 16;
    const float4* x1 = x0 + (size_t)half * 16;
    const ulonglong2* w1 = reinterpret_cast<const ulonglong2*>(sW1t);
#pragma unroll
    for (int k4 = 0; k4 < 16; k4++) {
        float4 v0 = x0[k4], v1 = x1[k4];
        float r0[4] = {v0.x, v0.y, v0.z, v0.w};
        float r1[4] = {v1.x, v1.y, v1.z, v1.w};
#pragma unroll
        for (int kk = 0; kk < 4; kk++) {
            const int k = k4 * 4 + kk;
            u64 d0 = dup2(r0[kk]);
            u64 d1 = dup2(r1[kk]);
#pragma unroll
            for (int q = 0; q < 8; q++) {
                ulonglong2 w = w1[k * 8 + q];
                a0[2 * q]     = fma2(d0, w.x, a0[2 * q]);
                a0[2 * q + 1] = fma2(d0, w.y, a0[2 * q + 1]);
                a1[2 * q]     = fma2(d1, w.x, a1[2 * q]);
                a1[2 * q + 1] = fma2(d1, w.y, a1[2 * q + 1]);
            }
        }
    }
    float h[2][32];
#pragma unroll
    for (int p = 0; p < 16; p++) {
        float2 f0 = unpack2(a0[p]);
        float2 f1 = unpack2(a1[p]);
        h[0][2 * p]     = fmaxf(f0.x, 0.0f);
        h[0][2 * p + 1] = fmaxf(f0.y, 0.0f);
        h[1][2 * p]     = fmaxf(f1.x, 0.0f);
        h[1][2 * p + 1] = fmaxf(f1.y, 0.0f);
    }

    // =================== layer 2: encoded = tanh(h @ W2^T + b2) ============
    u64 e[2][2];
    {
        const u64* bp = reinterpret_cast<const u64*>(sb2);
        e[0][0] = e[1][0] = bp[0];
        e[0][1] = e[1][1] = bp[1];
    }
    const ulonglong2* w2 = reinterpret_cast<const ulonglong2*>(sW2t);
#pragma unroll
    for (int k = 0; k < 32; k++) {
        ulonglong2 w = w2[k];
        u64 d0 = dup2(h[0][k]);
        u64 d1 = dup2(h[1][k]);
        e[0][0] = fma2(d0, w.x, e[0][0]);
        e[0][1] = fma2(d0, w.y, e[0][1]);
        e[1][0] = fma2(d1, w.x, e[1][0]);
        e[1][1] = fma2(d1, w.y, e[1][1]);
    }

    // circuit per row -> z[2][4]
    float z[2][4];
#pragma unroll
    for (int r = 0; r < 2; r++) {
        float2 f01 = unpack2(e[r][0]);
        float2 f23 = unpack2(e[r][1]);
        float enc[4] = {f01.x, f01.y, f23.x, f23.y};
        float ec[4], es[4];
#pragma unroll
        for (int i = 0; i < 4; i++) {
            float t = fast_tanh(enc[i]);
            __sincosf(0.5f * t, &es[i], &ec[i]);
        }
        float A[4] = {ec[0] * ec[1], ec[0] * es[1], es[0] * ec[1], es[0] * es[1]};
        float C[4] = {ec[2] * ec[3], ec[2] * es[3], es[2] * ec[3], es[2] * es[3]};
        float psi[16];
#pragma unroll
        for (int hi = 0; hi < 4; hi++)
#pragma unroll
            for (int lo = 0; lo < 4; lo++)
                psi[hi * 4 + lo] = A[hi] * C[lo];

#pragma unroll
        for (int layer = 0; layer < 2; layer++) {
            cnot_gate<0, 1>(psi);
            cnot_gate<1, 2>(psi);
            cnot_gate<2, 3>(psi);
            cnot_gate<3, 0>(psi);
            const int o = layer * 4;
            ry_gate<0>(psi, sqc[o + 0], sqs[o + 0]);
            ry_gate<1>(psi, sqc[o + 1], sqs[o + 1]);
            ry_gate<2>(psi, sqc[o + 2], sqs[o + 2]);
            ry_gate<3>(psi, sqc[o + 3], sqs[o + 3]);
        }

        float p[16];
#pragma unroll
        for (int i = 0; i < 16; i++) p[i] = psi[i] * psi[i];
        float d2[8], s2[8];
#pragma unroll
        for (int i = 0; i < 8; i++) { d2[i] = p[2 * i] - p[2 * i + 1]; s2[i] = p[2 * i] + p[2 * i + 1]; }
        z[r][3] = ((d2[0] + d2[1]) + (d2[2] + d2[3])) + ((d2[4] + d2[5]) + (d2[6] + d2[7]));
        float d4[4], s4[4];
#pragma unroll
        for (int i = 0; i < 4; i++) { d4[i] = s2[2 * i] - s2[2 * i + 1]; s4[i] = s2[2 * i] + s2[2 * i + 1]; }
        z[r][2] = (d4[0] + d4[1]) + (d4[2] + d4[3]);
        float d8[2] = {s4[0] - s4[1], s4[2] - s4[3]};
        float s8[2] = {s4[0] + s4[1], s4[2] + s4[3]};
        z[r][1] = d8[0] + d8[1];
        z[r][0] = s8[0] - s8[1];
    }

    // =================== head: h2 = relu(z @ H1^T + c1), packed over o =====
    u64 g0[16], g1[16];
    {
        const u64* bp = reinterpret_cast<const u64*>(sc1);
#pragma unroll
        for (int p = 0; p < 16; p++) { g0[p] = bp[p]; g1[p] = bp[p]; }
    }
    const ulonglong2* h1p = reinterpret_cast<const ulonglong2*>(sH1p);
#pragma unroll
    for (int k = 0; k < 4; k++) {
        u64 d0 = dup2(z[0][k]);
        u64 d1 = dup2(z[1][k]);
#pragma unroll
        for (int q = 0; q < 8; q++) {
            ulonglong2 w = h1p[k * 8 + q];
            g0[2 * q]     = fma2(d0, w.x, g0[2 * q]);
            g0[2 * q + 1] = fma2(d0, w.y, g0[2 * q + 1]);
            g1[2 * q]     = fma2(d1, w.x, g1[2 * q]);
            g1[2 * q + 1] = fma2(d1, w.y, g1[2 * q + 1]);
        }
    }
    float h2v[2][32];
#pragma unroll
    for (int p = 0; p < 16; p++) {
        float2 f0 = unpack2(g0[p]);
        float2 f1 = unpack2(g1[p]);
        h2v[0][2 * p]     = fmaxf(f0.x, 0.0f);
        h2v[0][2 * p + 1] = fmaxf(f0.y, 0.0f);
        h2v[1][2 * p]     = fmaxf(f1.x, 0.0f);
        h2v[1][2 * p + 1] = fmaxf(f1.y, 0.0f);
    }

    // =================== out = tanh(h2 @ H2^T + c2), packed over o =========
    u64 oa0[8], oa1[8];
    {
        const u64* bp = reinterpret_cast<const u64*>(sc2);
#pragma unroll
        for (int p = 0; p < 8; p++) { oa0[p] = bp[p]; oa1[p] = bp[p]; }
    }
    const ulonglong2* h2p = reinterpret_cast<const ulonglong2*>(sH2p);
#pragma unroll
    for (int k = 0; k < 32; k++) {
        u64 d0 = dup2(h2v[0][k]);
        u64 d1 = dup2(h2v[1][k]);
#pragma unroll
        for (int q = 0; q < 4; q++) {
            ulonglong2 w = h2p[k * 4 + q];
            oa0[2 * q]     = fma2(d0, w.x, oa0[2 * q]);
            oa0[2 * q + 1] = fma2(d0, w.y, oa0[2 * q + 1]);
            oa1[2 * q]     = fma2(d1, w.x, oa1[2 * q]);
            oa1[2 * q + 1] = fma2(d1, w.y, oa1[2 * q + 1]);
        }
    }

    float4* o0 = reinterpret_cast<float4*>(out) + (size_t)g * 4;
    float4* o1 = o0 + (size_t)half * 4;
#pragma unroll
    for (int t = 0; t < 4; t++) {
        float2 fa = unpack2(oa0[2 * t]);
        float2 fb = unpack2(oa0[2 * t + 1]);
        o0[t] = make_float4(fast_tanh(fa.x), fast_tanh(fa.y), fast_tanh(fb.x), fast_tanh(fb.y));
    }
#pragma unroll
    for (int t = 0; t < 4; t++) {
        float2 fa = unpack2(oa1[2 * t]);
        float2 fb = unpack2(oa1[2 * t + 1]);
        o1[t] = make_float4(fast_tanh(fa.x), fast_tanh(fa.y), fast_tanh(fb.x), fast_tanh(fb.y));
    }
}

extern "C" void kernel_launch(void* const* d_in, const int* in_sizes, int n_in,
                              void* d_out, int out_size) {
    const float* state = (const float*)d_in[0];
    const float* W1    = (const float*)d_in[1];
    const float* b1    = (const float*)d_in[2];
    const float* W2    = (const float*)d_in[3];
    const float* b2    = (const float*)d_in[4];
    const float* qp    = (const float*)d_in[5];
    const float* H1    = (const float*)d_in[6];
    const float* c1    = (const float*)d_in[7];
    const float* H2    = (const float*)d_in[8];
    const float* c2    = (const float*)d_in[9];

    const int B = in_sizes[0] / 64;
    const int half = B / 2;
    const int grid = (half + TPB - 1) / TPB;
    qnet_kernel<<<grid, TPB>>>(state, W1, b1, W2, b2, qp, H1, c1, H2, c2,
                               (float*)d_out, half);
}

// round 3
// speedup vs baseline: 1.9124x; 1.9124x over previous
#include <cuda_runtime.h>

#define TPB 256

typedef unsigned long long u64;

// ---------------------------------------------------------------------------
// Constant bank image (floats):
//  [0,2048)    W1T interleaved: W1T[k*32+j] = W1[j*64+k]   (output pairs adjacent)
//  [2048,2176) W2T:            W2T[k*4+i]  = W2[i*32+k]
//  [2176,2304) H1T:            H1T[k*32+o] = H1[o*4+k]
//  [2304,2816) H2T:            H2T[k*16+o] = H2[o*32+k]
//  [2816,2848) b1   [2848,2852) b2   [2852,2884) c1   [2884,2900) c2
//  [2900,2908) qcos [2908,2916) qsin
// ---------------------------------------------------------------------------
#define OFF_W1 0
#define OFF_W2 2048
#define OFF_H1 2176
#define OFF_H2 2304
#define OFF_B1 2816
#define OFF_B2 2848
#define OFF_C1 2852
#define OFF_C2 2884
#define OFF_QC 2900
#define OFF_QS 2908
#define CB_SIZE 2944

__constant__ float CB[CB_SIZE];
__device__ float g_stage[CB_SIZE];

// ---------------- packed f32x2 helpers --------------------------------------
__device__ __forceinline__ u64 dup2(float x) {
    u64 r;
    unsigned u = __float_as_uint(x);
    asm("mov.b64 %0, {%1, %1};" : "=l"(r) : "r"(u));
    return r;
}
__device__ __forceinline__ float2 unpack2(u64 v) {
    unsigned lo, hi;
    asm("mov.b64 {%0, %1}, %2;" : "=r"(lo), "=r"(hi) : "l"(v));
    return make_float2(__uint_as_float(lo), __uint_as_float(hi));
}
__device__ __forceinline__ u64 fma2(u64 a, u64 b, u64 c) {
    u64 d;
    asm("fma.rn.f32x2 %0, %1, %2, %3;" : "=l"(d) : "l"(a), "l"(b), "l"(c));
    return d;
}
__device__ __forceinline__ float fast_tanh(float x) {
    float e = __expf(2.0f * x);
    return 1.0f - __fdividef(2.0f, e + 1.0f);
}

// ---------------- 4-qubit real statevector (wire 0 = MSB) -------------------
template <int W>
__device__ __forceinline__ void ry_gate(float* psi, float c, float s) {
    const int bit = 8 >> W;
#pragma unroll
    for (int i = 0; i < 16; i++) {
        if ((i & bit) == 0) {
            const int j = i | bit;
            float a = psi[i], b = psi[j];
            psi[i] = fmaf(c, a, -s * b);
            psi[j] = fmaf(s, a, c * b);
        }
    }
}
template <int CTRL, int TGT>
__device__ __forceinline__ void cnot_gate(float* psi) {
    const int cb = 8 >> CTRL, tb = 8 >> TGT;
#pragma unroll
    for (int i = 0; i < 16; i++) {
        if ((i & cb) && !(i & tb)) {
            const int j = i | tb;
            float t = psi[i];
            psi[i] = psi[j];
            psi[j] = t;
        }
    }
}

// ---------------- prep: transpose weights into staging image ----------------
__global__ void prep_kernel(const float* __restrict__ W1, const float* __restrict__ W2,
                            const float* __restrict__ b1, const float* __restrict__ b2,
                            const float* __restrict__ qp, const float* __restrict__ H1,
                            const float* __restrict__ c1, const float* __restrict__ H2,
                            const float* __restrict__ c2) {
    const int t = threadIdx.x;
#pragma unroll
    for (int i = t; i < 2048; i += TPB) {
        int j = i >> 6, k = i & 63;
        g_stage[OFF_W1 + k * 32 + j] = W1[i];
    }
    if (t < 128) {
        int i = t >> 5, k = t & 31;
        g_stage[OFF_W2 + k * 4 + i] = W2[t];
    }
    if (t < 128) {
        int o = t >> 2, k = t & 3;
        g_stage[OFF_H1 + k * 32 + o] = H1[t];
    }
#pragma unroll
    for (int i = t; i < 512; i += TPB) {
        int o = i >> 5, k = i & 31;
        g_stage[OFF_H2 + k * 16 + o] = H2[i];
    }
    if (t < 32) g_stage[OFF_B1 + t] = b1[t];
    if (t < 4)  g_stage[OFF_B2 + t] = b2[t];
    if (t < 32) g_stage[OFF_C1 + t] = c1[t];
    if (t < 16) g_stage[OFF_C2 + t] = c2[t];
    if (t < 8) {
        float cc, ss;
        sincosf(0.5f * qp[t], &ss, &cc);
        g_stage[OFF_QC + t] = cc;
        g_stage[OFF_QS + t] = ss;
    }
}

// ---------------- main kernel: one batch row per thread ---------------------
__global__ __launch_bounds__(TPB) void qnet_kernel(
    const float* __restrict__ state, float* __restrict__ out, int B)
{
    const int b = blockIdx.x * TPB + threadIdx.x;
    if (b >= B) return;

    const ulonglong2* __restrict__ w1 = reinterpret_cast<const ulonglong2*>(CB + OFF_W1);
    const ulonglong2* __restrict__ w2 = reinterpret_cast<const ulonglong2*>(CB + OFF_W2);
    const ulonglong2* __restrict__ h1 = reinterpret_cast<const ulonglong2*>(CB + OFF_H1);
    const ulonglong2* __restrict__ h2w = reinterpret_cast<const ulonglong2*>(CB + OFF_H2);

    // ===== layer 1: h = relu(x @ W1^T + b1), FFMA2 packed over output pairs ==
    u64 a[16];
    {
        const u64* bp = reinterpret_cast<const u64*>(CB + OFF_B1);
#pragma unroll
        for (int p = 0; p < 16; p++) a[p] = bp[p];
    }
    const float4* xp = reinterpret_cast<const float4*>(state) + (size_t)b * 16;
#pragma unroll
    for (int k4 = 0; k4 < 16; k4++) {
        float4 v = xp[k4];
        float r[4] = {v.x, v.y, v.z, v.w};
#pragma unroll
        for (int kk = 0; kk < 4; kk++) {
            const int k = k4 * 4 + kk;
            u64 d = dup2(r[kk]);
#pragma unroll
            for (int q = 0; q < 8; q++) {
                ulonglong2 w = w1[k * 8 + q];
                a[2 * q]     = fma2(d, w.x, a[2 * q]);
                a[2 * q + 1] = fma2(d, w.y, a[2 * q + 1]);
            }
        }
    }
    float h[32];
#pragma unroll
    for (int p = 0; p < 16; p++) {
        float2 f = unpack2(a[p]);
        h[2 * p]     = fmaxf(f.x, 0.0f);
        h[2 * p + 1] = fmaxf(f.y, 0.0f);
    }

    // ===== layer 2: encoded = tanh(h @ W2^T + b2) ============================
    u64 e0, e1;
    {
        const u64* bp = reinterpret_cast<const u64*>(CB + OFF_B2);
        e0 = bp[0];
        e1 = bp[1];
    }
#pragma unroll
    for (int k = 0; k < 32; k += 2) {
        ulonglong2 wa = w2[k >> 1];          // covers outputs (0,1),(2,3) for k
        u64 d = dup2(h[k]);
        e0 = fma2(d, wa.x, e0);
        e1 = fma2(d, wa.y, e1);
        // next k uses the following ulonglong2... need per-k pair layout:
        // W2T is [k][i]: 4 floats per k = one u64 pair per 2 outputs; one
        // ulonglong2 = one full k row. So index is k, not k/2 — fix below.
    }
    // NOTE: the loop above is wrong-layout-safe only if w2[k] indexes rows.
    // Redo cleanly (compiler removes the dead loop result):
    {
        const u64* bp = reinterpret_cast<const u64*>(CB + OFF_B2);
        e0 = bp[0];
        e1 = bp[1];
#pragma unroll
        for (int k = 0; k < 32; k++) {
            ulonglong2 wa = w2[k];           // row k: outputs (0,1) and (2,3)
            u64 d = dup2(h[k]);
            e0 = fma2(d, wa.x, e0);
            e1 = fma2(d, wa.y, e1);
        }
    }

    // ===== quantum circuit ===================================================
    float z[4];
    {
        float2 f01 = unpack2(e0);
        float2 f23 = unpack2(e1);
        float enc[4] = {f01.x, f01.y, f23.x, f23.y};
        float ec[4], es[4];
#pragma unroll
        for (int i = 0; i < 4; i++) {
            float t = fast_tanh(enc[i]);
            __sincosf(0.5f * t, &es[i], &ec[i]);
        }
        float A[4] = {ec[0] * ec[1], ec[0] * es[1], es[0] * ec[1], es[0] * es[1]};
        float C[4] = {ec[2] * ec[3], ec[2] * es[3], es[2] * ec[3], es[2] * es[3]};
        float psi[16];
#pragma unroll
        for (int hi = 0; hi < 4; hi++)
#pragma unroll
            for (int lo = 0; lo < 4; lo++)
                psi[hi * 4 + lo] = A[hi] * C[lo];

#pragma unroll
        for (int layer = 0; layer < 2; layer++) {
            cnot_gate<0, 1>(psi);
            cnot_gate<1, 2>(psi);
            cnot_gate<2, 3>(psi);
            cnot_gate<3, 0>(psi);
            const int o = layer * 4;
            ry_gate<0>(psi, CB[OFF_QC + o + 0], CB[OFF_QS + o + 0]);
            ry_gate<1>(psi, CB[OFF_QC + o + 1], CB[OFF_QS + o + 1]);
            ry_gate<2>(psi, CB[OFF_QC + o + 2], CB[OFF_QS + o + 2]);
            ry_gate<3>(psi, CB[OFF_QC + o + 3], CB[OFF_QS + o + 3]);
        }

        float p[16];
#pragma unroll
        for (int i = 0; i < 16; i++) p[i] = psi[i] * psi[i];
        float d2[8], s2[8];
#pragma unroll
        for (int i = 0; i < 8; i++) { d2[i] = p[2 * i] - p[2 * i + 1]; s2[i] = p[2 * i] + p[2 * i + 1]; }
        z[3] = ((d2[0] + d2[1]) + (d2[2] + d2[3])) + ((d2[4] + d2[5]) + (d2[6] + d2[7]));
        float d4[4], s4[4];
#pragma unroll
        for (int i = 0; i < 4; i++) { d4[i] = s2[2 * i] - s2[2 * i + 1]; s4[i] = s2[2 * i] + s2[2 * i + 1]; }
        z[2] = (d4[0] + d4[1]) + (d4[2] + d4[3]);
        float d8[2] = {s4[0] - s4[1], s4[2] - s4[3]};
        float s8[2] = {s4[0] + s4[1], s4[2] + s4[3]};
        z[1] = d8[0] + d8[1];
        z[0] = s8[0] - s8[1];
    }

    // ===== head: h2 = relu(z @ H1^T + c1), packed over output pairs ==========
    u64 g[16];
    {
        const u64* bp = reinterpret_cast<const u64*>(CB + OFF_C1);
#pragma unroll
        for (int p = 0; p < 16; p++) g[p] = bp[p];
    }
#pragma unroll
    for (int k = 0; k < 4; k++) {
        u64 d = dup2(z[k]);
#pragma unroll
        for (int q = 0; q < 8; q++) {
            ulonglong2 w = h1[k * 8 + q];
            g[2 * q]     = fma2(d, w.x, g[2 * q]);
            g[2 * q + 1] = fma2(d, w.y, g[2 * q + 1]);
        }
    }
    float hv[32];
#pragma unroll
    for (int p = 0; p < 16; p++) {
        float2 f = unpack2(g[p]);
        hv[2 * p]     = fmaxf(f.x, 0.0f);
        hv[2 * p + 1] = fmaxf(f.y, 0.0f);
    }

    // ===== out = tanh(h2 @ H2^T + c2), packed over output pairs ==============
    u64 oa[8];
    {
        const u64* bp = reinterpret_cast<const u64*>(CB + OFF_C2);
#pragma unroll
        for (int p = 0; p < 8; p++) oa[p] = bp[p];
    }
#pragma unroll
    for (int k = 0; k < 32; k++) {
        u64 d = dup2(hv[k]);
#pragma unroll
        for (int q = 0; q < 4; q++) {
            ulonglong2 w = h2w[k * 4 + q];
            oa[2 * q]     = fma2(d, w.x, oa[2 * q]);
            oa[2 * q + 1] = fma2(d, w.y, oa[2 * q + 1]);
        }
    }

    float4* o4 = reinterpret_cast<float4*>(out) + (size_t)b * 4;
#pragma unroll
    for (int t = 0; t < 4; t++) {
        float2 fa = unpack2(oa[2 * t]);
        float2 fb = unpack2(oa[2 * t + 1]);
        o4[t] = make_float4(fast_tanh(fa.x), fast_tanh(fa.y),
                            fast_tanh(fb.x), fast_tanh(fb.y));
    }
}

extern "C" void kernel_launch(void* const* d_in, const int* in_sizes, int n_in,
                              void* d_out, int out_size) {
    const float* state = (const float*)d_in[0];
    const float* W1    = (const float*)d_in[1];
    const float* b1    = (const float*)d_in[2];
    const float* W2    = (const float*)d_in[3];
    const float* b2    = (const float*)d_in[4];
    const float* qp    = (const float*)d_in[5];
    const float* H1    = (const float*)d_in[6];
    const float* c1    = (const float*)d_in[7];
    const float* H2    = (const float*)d_in[8];
    const float* c2    = (const float*)d_in[9];

    prep_kernel<<<1, TPB>>>(W1, W2, b1, b2, qp, H1, c1, H2, c2);

    void* dst = nullptr;
    void* src = nullptr;
    cudaGetSymbolAddress(&dst, CB);
    cudaGetSymbolAddress(&src, g_stage);
    cudaMemcpyAsync(dst, src, CB_SIZE * sizeof(float), cudaMemcpyDeviceToDevice);

    const int B = in_sizes[0] / 64;
    const int grid = (B + TPB - 1) / TPB;
    qnet_kernel<<<grid, TPB>>>(state, (float*)d_out, B);
}